// round 6
// baseline (speedup 1.0000x reference)
#include <cuda_runtime.h>
#include <cuda_bf16.h>
#include <cstdint>

#define B_ 128
#define K_ 65536
#define C_ 768
#define POSCAP 4096
#define FULLW 0xffffffffu
#define TILE 4096

// ---------------- device scratch ----------------
static __device__ unsigned g_keysA[(size_t)B_ * K_];
static __device__ unsigned g_keysB[(size_t)B_ * K_];
static __device__ float    g_cos[(size_t)B_ * K_];
static __device__ float    g_posv[B_ * POSCAP];
static __device__ unsigned g_hist[B_][3][256];
static __device__ int      g_neg_cnt[B_];
static __device__ int      g_pos_wr[B_];
static __device__ int      g_minpos;
static __device__ int      g_maxpos;
static __device__ int      g_pos_min;
static __device__ int      g_neg_min;
static __device__ int      g_reps;
static __device__ int      g_lstride;
static __device__ float    g_poscat[B_ * 32];
static __device__ __align__(16) __nv_bfloat16 g_Ah[B_ * C_];
static __device__ __align__(16) __nv_bfloat16 g_Al[B_ * C_];
static __device__ __align__(16) __nv_bfloat16 g_Bh[(size_t)K_ * C_];
static __device__ __align__(16) __nv_bfloat16 g_Bl[(size_t)K_ * C_];

__device__ __forceinline__ unsigned flip_f32(float v) {
    unsigned b = __float_as_uint(v);
    return (b & 0x80000000u) ? ~b : (b | 0x80000000u);
}
__device__ __forceinline__ float unflip_f32(unsigned u) {
    unsigned b = (u & 0x80000000u) ? (u & 0x7fffffffu) : ~u;
    return __uint_as_float(b);
}
__device__ __forceinline__ uint32_t smem_u32(const void* p) {
    uint32_t a;
    asm("{ .reg .u64 t; cvta.to.shared.u64 t, %1; cvt.u32.u64 %0, t; }" : "=r"(a) : "l"(p));
    return a;
}
__device__ __forceinline__ void ldsm4(uint32_t* r, uint32_t addr) {
    asm volatile("ldmatrix.sync.aligned.m8n8.x4.shared.b16 {%0,%1,%2,%3}, [%4];"
                 : "=r"(r[0]), "=r"(r[1]), "=r"(r[2]), "=r"(r[3]) : "r"(addr));
}
__device__ __forceinline__ void mma16816(float* c, const uint32_t* a, const uint32_t* b) {
    asm volatile("mma.sync.aligned.m16n8k16.row.col.f32.bf16.bf16.f32 "
                 "{%0,%1,%2,%3}, {%4,%5,%6,%7}, {%8,%9}, {%0,%1,%2,%3};"
                 : "+f"(c[0]), "+f"(c[1]), "+f"(c[2]), "+f"(c[3])
                 : "r"(a[0]), "r"(a[1]), "r"(a[2]), "r"(a[3]), "r"(b[0]), "r"(b[1]));
}

// ---------------- init: zero counters/hists + label width detect ----------------
__global__ void k_init(const unsigned* __restrict__ lQ) {
    int b = blockIdx.x, t = threadIdx.x;
    for (int z = t; z < 768; z += 256) ((unsigned*)g_hist[b])[z] = 0;
    if (t == 0) { g_neg_cnt[b] = 0; g_pos_wr[b] = 0; }
    if (b == 0) {
        if (t == 0) { g_minpos = 1 << 30; g_maxpos = 0; }
        unsigned v = 0;
        for (int i = 2 * t + 1; i < 16384; i += 512) v |= lQ[i];
        __shared__ unsigned sh[256];
        sh[t] = v; __syncthreads();
        for (int o = 128; o; o >>= 1) { if (t < o) sh[t] |= sh[t + o]; __syncthreads(); }
        if (t == 0) g_lstride = (sh[0] == 0u) ? 2 : 1;
    }
}

// ---------------- per-row positive counts ----------------
__global__ void k_count(const unsigned* __restrict__ lq, const unsigned* __restrict__ lQ) {
    int b = blockIdx.x, t = threadIdx.x, s = g_lstride;
    unsigned my = lq[b * s];
    int c = 0;
    for (int k = t; k < K_; k += 256) c += (lQ[(size_t)k * s] == my);
    __shared__ int sh[256];
    sh[t] = c; __syncthreads();
    for (int o = 128; o; o >>= 1) { if (t < o) sh[t] += sh[t + o]; __syncthreads(); }
    if (t == 0) { atomicMin(&g_minpos, sh[0]); atomicMax(&g_maxpos, sh[0]); }
}

__global__ void k_fin(const int* __restrict__ tkp) {
    int tk = *tkp;
    g_pos_min = g_minpos;
    g_neg_min = K_ - g_maxpos;
    int t = (tk < g_minpos) ? tk : g_minpos;
    g_reps = t + 1;
}

// ---------------- fp32 -> bf16 hi/lo conversion ----------------
__device__ __forceinline__ unsigned pk2(__nv_bfloat16 a, __nv_bfloat16 b) {
    __nv_bfloat162 t; t.x = a; t.y = b;
    return *(unsigned*)&t;
}
__global__ __launch_bounds__(256) void k_convA(const float* __restrict__ A) {
    int i = blockIdx.x * 256 + threadIdx.x;
    if (i < B_ * C_) {
        float x = A[i];
        __nv_bfloat16 h = __float2bfloat16(x);
        g_Ah[i] = h;
        g_Al[i] = __float2bfloat16(x - __bfloat162float(h));
    }
}
__global__ __launch_bounds__(512) void k_convB(const float* __restrict__ Bq) {
    size_t i4 = (size_t)blockIdx.x * 512 + threadIdx.x;
    float4 x = ((const float4*)Bq)[i4];
    __nv_bfloat16 h0 = __float2bfloat16(x.x), h1 = __float2bfloat16(x.y);
    __nv_bfloat16 h2 = __float2bfloat16(x.z), h3 = __float2bfloat16(x.w);
    __nv_bfloat16 l0 = __float2bfloat16(x.x - __bfloat162float(h0));
    __nv_bfloat16 l1 = __float2bfloat16(x.y - __bfloat162float(h1));
    __nv_bfloat16 l2 = __float2bfloat16(x.z - __bfloat162float(h2));
    __nv_bfloat16 l3 = __float2bfloat16(x.w - __bfloat162float(h3));
    ((uint2*)g_Bh)[i4] = make_uint2(pk2(h0, h1), pk2(h2, h3));
    ((uint2*)g_Bl)[i4] = make_uint2(pk2(l0, l1), pk2(l2, l3));
}

// ---------------- mma.sync bf16 3-split GEMM: D[128, 65536] = A * B^T ----------------
#define SPAD 40  // bf16 row stride (80B): ldmatrix bank-conflict-free
__global__ __launch_bounds__(256) void k_gemm_mma() {
    __shared__ __align__(16) __nv_bfloat16 sAh[128 * SPAD];
    __shared__ __align__(16) __nv_bfloat16 sAl[128 * SPAD];
    __shared__ __align__(16) __nv_bfloat16 sBh[128 * SPAD];
    __shared__ __align__(16) __nv_bfloat16 sBl[128 * SPAD];
    int t = threadIdx.x, wid = t >> 5, lane = t & 31;
    int nt0 = blockIdx.x * 128;
    int m0 = (wid & 3) * 32;
    int n0w = (wid >> 2) * 64;

    float acc[2][8][4];
#pragma unroll
    for (int i = 0; i < 2; i++)
#pragma unroll
        for (int j = 0; j < 8; j++)
#pragma unroll
            for (int q = 0; q < 4; q++) acc[i][j][q] = 0.f;

    uint32_t bAh = smem_u32(sAh), bAl = smem_u32(sAl);
    uint32_t bBh = smem_u32(sBh), bBl = smem_u32(sBl);

    int r = t >> 1, hf = (t & 1) * 16;
    // A frag smem offset pieces (bytes): row m0+mt*16+(lane&15), col ks*16+(lane>>4)*8
    int aRow = m0 + (lane & 15);
    int aColOff = (lane >> 4) * 8;
    // B frag: lanes0-7:(n+l,k0) 8-15:(n+l,k+8) 16-23:(n+8+l,k0) 24-31:(n+8+l,k+8)
    int bRow = n0w + (lane & 7) + ((lane & 16) ? 8 : 0);
    int bColOff = (lane & 8);

    for (int ch = 0; ch < 24; ch++) {
        int k0 = ch * 32;
        {
            const __nv_bfloat16* pAh = g_Ah + (size_t)r * C_ + k0 + hf;
            const __nv_bfloat16* pAl = g_Al + (size_t)r * C_ + k0 + hf;
            const __nv_bfloat16* pBh = g_Bh + (size_t)(nt0 + r) * C_ + k0 + hf;
            const __nv_bfloat16* pBl = g_Bl + (size_t)(nt0 + r) * C_ + k0 + hf;
            int so = r * SPAD + hf;
            *(uint4*)&sAh[so] = *(const uint4*)pAh;
            *(uint4*)&sAh[so + 8] = *(const uint4*)(pAh + 8);
            *(uint4*)&sAl[so] = *(const uint4*)pAl;
            *(uint4*)&sAl[so + 8] = *(const uint4*)(pAl + 8);
            *(uint4*)&sBh[so] = *(const uint4*)pBh;
            *(uint4*)&sBh[so + 8] = *(const uint4*)(pBh + 8);
            *(uint4*)&sBl[so] = *(const uint4*)pBl;
            *(uint4*)&sBl[so + 8] = *(const uint4*)(pBl + 8);
        }
        __syncthreads();

#pragma unroll
        for (int ks = 0; ks < 2; ks++) {
            int kk = ks * 16;
            uint32_t ah[2][4], al[2][4];
#pragma unroll
            for (int mt = 0; mt < 2; mt++) {
                uint32_t off = (uint32_t)(((aRow + mt * 16) * SPAD + kk + aColOff) * 2);
                ldsm4(ah[mt], bAh + off);
                ldsm4(al[mt], bAl + off);
            }
#pragma unroll
            for (int np = 0; np < 4; np++) {
                uint32_t bh[4], bl[4];
                uint32_t off = (uint32_t)(((bRow + np * 16) * SPAD + kk + bColOff) * 2);
                ldsm4(bh, bBh + off);
                ldsm4(bl, bBl + off);
#pragma unroll
                for (int mt = 0; mt < 2; mt++) {
                    mma16816(acc[mt][np * 2], ah[mt], bh);
                    mma16816(acc[mt][np * 2], ah[mt], bl);
                    mma16816(acc[mt][np * 2], al[mt], bh);
                    mma16816(acc[mt][np * 2 + 1], ah[mt], bh + 2);
                    mma16816(acc[mt][np * 2 + 1], ah[mt], bl + 2);
                    mma16816(acc[mt][np * 2 + 1], al[mt], bh + 2);
                }
            }
        }
        __syncthreads();
    }

    // epilogue: acc -> g_cos
#pragma unroll
    for (int mt = 0; mt < 2; mt++) {
        int mr = m0 + mt * 16 + (lane >> 2);
#pragma unroll
        for (int nt = 0; nt < 8; nt++) {
            int col = nt0 + n0w + nt * 8 + (lane & 3) * 2;
            float2 v0 = make_float2(acc[mt][nt][0], acc[mt][nt][1]);
            float2 v1 = make_float2(acc[mt][nt][2], acc[mt][nt][3]);
            *(float2*)&g_cos[(size_t)mr * K_ + col] = v0;
            *(float2*)&g_cos[(size_t)(mr + 8) * K_ + col] = v1;
        }
    }
}

// ---------------- partition + 3-pass digit histograms ----------------
__global__ __launch_bounds__(256) void k_part(const unsigned* __restrict__ lq,
                                              const unsigned* __restrict__ lQ) {
    __shared__ unsigned h[3 * 256];
    int row = blockIdx.x >> 3;
    int chunk = blockIdx.x & 7;
    int t = threadIdx.x, lane = t & 31;
    unsigned ltm = (1u << lane) - 1u;
    int s = g_lstride;
    unsigned myl = lq[row * s];
    for (int z = t; z < 768; z += 256) h[z] = 0;
    __syncthreads();
    const float* cosr = g_cos + (size_t)row * K_ + chunk * 8192;
    for (int q = 0; q < 32; q++) {
        int col = chunk * 8192 + q * 256 + t;
        float v = cosr[q * 256 + t];
        bool isPos = (lQ[(size_t)col * s] == myl);
        unsigned negm = __ballot_sync(FULLW, !isPos);
        if (!isPos) {
            int r = __popc(negm & ltm);
            int base = 0;
            if (r == 0) base = atomicAdd(&g_neg_cnt[row], __popc(negm));
            base = __shfl_sync(negm, base, __ffs(negm) - 1);
            unsigned u = flip_f32(v);
            g_keysA[((size_t)row << 16) + base + r] = u;
            atomicAdd(&h[0 * 256 + ((u >> 8) & 255u)], 1u);
            atomicAdd(&h[1 * 256 + ((u >> 16) & 255u)], 1u);
            atomicAdd(&h[2 * 256 + ((u >> 24) & 255u)], 1u);
        } else {
            unsigned posm = ~negm;
            int r = __popc(posm & ltm);
            int base = 0;
            if (r == 0) base = atomicAdd(&g_pos_wr[row], __popc(posm));
            base = __shfl_sync(posm, base, __ffs(posm) - 1);
            if (base + r < POSCAP) g_posv[row * POSCAP + base + r] = v;
        }
    }
    __syncthreads();
    for (int z = t; z < 768; z += 256) {
        unsigned c = h[z];
        if (c) atomicAdd(&((unsigned*)g_hist[row])[z], c);
    }
}

// ---------------- stable LSD radix, 3x8-bit over bits [8:32), 4 keys/thread/tile ----------------
__global__ __launch_bounds__(1024) void k_radix() {
    int b = blockIdx.x, t = threadIdx.x;
    int lane = t & 31, w = t >> 5;
    unsigned ltm = (1u << lane) - 1u;
    int n = g_neg_cnt[b];
    unsigned* bufA = g_keysA + ((size_t)b << 16);
    unsigned* bufB = g_keysB + ((size_t)b << 16);

    __shared__ unsigned binbase[256];
    __shared__ unsigned tstart[256];
    __shared__ unsigned tiletot[256];
    __shared__ __align__(16) unsigned short whist[8484];
    __shared__ __align__(16) unsigned skey[TILE];

    int ntile = (n + TILE - 1) / TILE;
    for (int pass = 0; pass < 3; pass++) {
        const unsigned* src = (pass & 1) ? bufB : bufA;
        unsigned*       dst = (pass & 1) ? bufA : bufB;
        int sh = 8 + pass * 8;

        if (w == 0) {
            unsigned vloc[8], tot = 0;
#pragma unroll
            for (int c = 0; c < 8; c++) { unsigned x = g_hist[b][pass][lane * 8 + c]; vloc[c] = tot; tot += x; }
            unsigned e = tot;
#pragma unroll
            for (int o = 1; o < 32; o <<= 1) { unsigned y = __shfl_up_sync(FULLW, e, o); if (lane >= o) e += y; }
            e -= tot;
#pragma unroll
            for (int c = 0; c < 8; c++) binbase[lane * 8 + c] = e + vloc[c];
        }
        __syncthreads();

        for (int tt = 0; tt < ntile; tt++) {
            int base = tt * TILE;
            int tn = n - base; if (tn > TILE) tn = TILE;

            for (int z = t; z < 4242; z += 1024) ((unsigned*)whist)[z] = 0;
            __syncthreads();

            unsigned key[4], lr[4]; int dg[4];
#pragma unroll
            for (int q = 0; q < 4; q++) {
                int idx = base + w * 128 + q * 32 + lane;
                unsigned d = 256u;
                if (idx < n) { key[q] = src[idx]; d = (key[q] >> sh) & 255u; }
                dg[q] = (int)d;
                unsigned m = __match_any_sync(FULLW, d);
                unsigned r = __popc(m & ltm);
                int leader = __ffs(m) - 1;
                unsigned old = 0;
                if (r == 0) {
                    old = whist[d * 33 + w];
                    whist[d * 33 + w] = (unsigned short)(old + __popc(m));
                }
                old = __shfl_sync(m, old, leader);
                lr[q] = old + r;
                __syncwarp();
            }
            __syncthreads();

            {
                int bd = w * 8;
                unsigned v[8], o8[8];
#pragma unroll
                for (int q = 0; q < 8; q++) { v[q] = whist[(bd + q) * 33 + lane]; o8[q] = v[q]; }
#pragma unroll
                for (int o = 1; o < 32; o <<= 1) {
#pragma unroll
                    for (int q = 0; q < 8; q++) {
                        unsigned y = __shfl_up_sync(FULLW, v[q], o);
                        if (lane >= o) v[q] += y;
                    }
                }
#pragma unroll
                for (int q = 0; q < 8; q++) {
                    whist[(bd + q) * 33 + lane] = (unsigned short)(v[q] - o8[q]);
                    if (lane == 31) tiletot[bd + q] = v[q];
                }
            }
            __syncthreads();

            if (w == 0) {
                unsigned vloc[8], tot = 0;
#pragma unroll
                for (int c = 0; c < 8; c++) { unsigned x = tiletot[lane * 8 + c]; vloc[c] = tot; tot += x; }
                unsigned e = tot;
#pragma unroll
                for (int o = 1; o < 32; o <<= 1) { unsigned y = __shfl_up_sync(FULLW, e, o); if (lane >= o) e += y; }
                e -= tot;
#pragma unroll
                for (int c = 0; c < 8; c++) tstart[lane * 8 + c] = e + vloc[c];
            }
            __syncthreads();

#pragma unroll
            for (int q = 0; q < 4; q++) {
                if (dg[q] < 256) {
                    unsigned p = tstart[dg[q]] + (unsigned)whist[dg[q] * 33 + w] + lr[q];
                    skey[p] = key[q];
                }
            }
            __syncthreads();

            {
                uint4 kk = *(const uint4*)&skey[t * 4];
                unsigned ks[4] = {kk.x, kk.y, kk.z, kk.w};
                int j0 = t * 4;
#pragma unroll
                for (int q = 0; q < 4; q++) {
                    int j = j0 + q;
                    if (j < tn) {
                        unsigned kq = ks[q];
                        unsigned d = (kq >> sh) & 255u;
                        dst[binbase[d] + (unsigned)j - tstart[d]] = kq;
                    }
                }
            }
            __syncthreads();
            if (t < 256) binbase[t] += tiletot[t];
            __syncthreads();
        }
    }
}

// ---------------- positives: smem bitonic sort (4096), emit pos_cat ----------------
__global__ __launch_bounds__(256) void k_possort() {
    __shared__ float s[4096];
    int b = blockIdx.x, t = threadIdx.x;
    int n = g_pos_wr[b];
    if (n > POSCAP) n = POSCAP;
    float ninf = __int_as_float(0xff800000);
    for (int i = t; i < 4096; i += 256)
        s[i] = (i < n) ? g_posv[b * POSCAP + i] : ninf;
    __syncthreads();
    for (int kk = 2; kk <= 4096; kk <<= 1) {
        for (int j = kk >> 1; j > 0; j >>= 1) {
            for (int i = t; i < 4096; i += 256) {
                int l = i ^ j;
                if (l > i) {
                    float a = s[i], c = s[l];
                    bool up = ((i & kk) == 0);
                    if (up ? (a > c) : (a < c)) { s[i] = c; s[l] = a; }
                }
            }
            __syncthreads();
        }
    }
    if (t == 0) {
        int tk = g_reps - 1;
        for (int j = 0; j < tk; j++) g_poscat[b * 32 + j] = s[4095 - j];
        g_poscat[b * 32 + tk] = s[4095 - (g_pos_min - 1)];
    }
}

// ---------------- writer: smem-broadcast, 4 segment-CTAs per b-row ----------------
__global__ __launch_bounds__(512) void k_write(float* __restrict__ out) {
    __shared__ __align__(16) float s[4096];
    int b = blockIdx.x >> 2;
    int seg = blockIdx.x & 3;
    int t = threadIdx.x;
    int reps = g_reps, nm = g_neg_min, cnt = g_neg_cnt[b];
    size_t W = (size_t)nm + 1;
    const unsigned* asc = g_keysB + ((size_t)b << 16);
    const float invT = 1.0f / 0.3f;

    if (seg == 0 && t < reps)
        out[(size_t)(b * reps + t) * W] = g_poscat[b * 32 + t] * invT;

    int per = (nm + 3) >> 2;
    int i0 = seg * per;
    int i1 = i0 + per; if (i1 > nm) i1 = nm;

    for (int c0 = i0; c0 < i1; c0 += 4096) {
        int len = i1 - c0; if (len > 4096) len = 4096;
        int glo = cnt - c0 - len;
        for (int u = t; u < len; u += 512)
            s[len - 1 - u] = unflip_f32(asc[glo + u]) * invT;
        __syncthreads();
        for (int j = 0; j < reps; j++) {
            size_t doff = (size_t)(b * reps + j) * W + 1 + c0;
            float* dst = out + doff;
            int head = (int)((4 - (doff & 3)) & 3); if (head > len) head = len;
            for (int u = t; u < head; u += 512) dst[u] = s[u];
            int nb = (len - head) >> 2;
            for (int u = t; u < nb; u += 512) {
                int p = head + u * 4;
                float4 v; v.x = s[p]; v.y = s[p + 1]; v.z = s[p + 2]; v.w = s[p + 3];
                *(float4*)&dst[p] = v;
            }
            for (int u = head + nb * 4 + t; u < len; u += 512) dst[u] = s[u];
        }
        __syncthreads();
    }
}

// ---------------- launch ----------------
extern "C" void kernel_launch(void* const* d_in, const int* in_sizes, int n_in,
                              void* d_out, int out_size) {
    const float*    A  = (const float*)d_in[0];
    const float*    Bq = (const float*)d_in[1];
    const unsigned* lq = (const unsigned*)d_in[2];
    const unsigned* lQ = (const unsigned*)d_in[3];
    const int*      tk = (const int*)d_in[4];
    float* out = (float*)d_out;
    (void)in_sizes; (void)n_in; (void)out_size;

    k_init<<<B_, 256>>>(lQ);
    k_count<<<B_, 256>>>(lq, lQ);
    k_fin<<<1, 1>>>(tk);
    k_convA<<<(B_ * C_ + 255) / 256, 256>>>(A);
    k_convB<<<(int)(((size_t)K_ * C_ / 4 + 511) / 512), 512>>>(Bq);
    k_gemm_mma<<<K_ / 128, 256>>>();
    k_part<<<B_ * 8, 256>>>(lq, lQ);
    k_radix<<<B_, 1024>>>();
    k_possort<<<B_, 256>>>();
    k_write<<<B_ * 4, 512>>>(out);
}

// round 8
// speedup vs baseline: 1.1916x; 1.1916x over previous
#include <cuda_runtime.h>
#include <cstdint>

#define B_ 128
#define K_ 65536
#define C_ 768
#define POSCAP 4096
#define FULLW 0xffffffffu
#define TILE 4096

// ---------------- device scratch ----------------
static __device__ unsigned g_keysA[(size_t)B_ * K_];
static __device__ unsigned g_keysB[(size_t)B_ * K_];
static __device__ float    g_cos[(size_t)B_ * K_];
static __device__ float    g_posv[B_ * POSCAP];
static __device__ unsigned g_qh[B_][4][256];
static __device__ int      g_neg_cnt[B_];
static __device__ int      g_pos_wr[B_];
static __device__ int      g_minpos;
static __device__ int      g_maxpos;
static __device__ int      g_pos_min;
static __device__ int      g_neg_min;
static __device__ int      g_reps;
static __device__ int      g_lstride;
static __device__ float    g_poscat[B_ * 32];

__device__ __forceinline__ unsigned flip_f32(float v) {
    unsigned b = __float_as_uint(v);
    return (b & 0x80000000u) ? ~b : (b | 0x80000000u);
}
__device__ __forceinline__ float unflip_f32(unsigned u) {
    unsigned b = (u & 0x80000000u) ? (u & 0x7fffffffu) : ~u;
    return __uint_as_float(b);
}

#define PACK2(dst, lo, hi) asm("mov.b64 %0, {%1, %2};" : "=l"(dst) : "f"(lo), "f"(hi))
#define FMA2(d, a, b)      asm("fma.rn.f32x2 %0, %1, %2, %0;" : "+l"(d) : "l"(a), "l"(b))

// ---------------- init ----------------
__global__ void k_init(const unsigned* __restrict__ lQ) {
    int b = blockIdx.x, t = threadIdx.x;
    if (t == 0) { g_neg_cnt[b] = 0; g_pos_wr[b] = 0; }
    if (b == 0) {
        if (t == 0) { g_minpos = 1 << 30; g_maxpos = 0; }
        unsigned v = 0;
        for (int i = 2 * t + 1; i < 16384; i += 512) v |= lQ[i];
        __shared__ unsigned sh[256];
        sh[t] = v; __syncthreads();
        for (int o = 128; o; o >>= 1) { if (t < o) sh[t] |= sh[t + o]; __syncthreads(); }
        if (t == 0) g_lstride = (sh[0] == 0u) ? 2 : 1;
    }
}

// ---------------- per-row positive counts ----------------
__global__ void k_count(const unsigned* __restrict__ lq, const unsigned* __restrict__ lQ) {
    int b = blockIdx.x, t = threadIdx.x, s = g_lstride;
    unsigned my = lq[b * s];
    int c = 0;
    for (int k = t; k < K_; k += 256) c += (lQ[(size_t)k * s] == my);
    __shared__ int sh[256];
    sh[t] = c; __syncthreads();
    for (int o = 128; o; o >>= 1) { if (t < o) sh[t] += sh[t + o]; __syncthreads(); }
    if (t == 0) { atomicMin(&g_minpos, sh[0]); atomicMax(&g_maxpos, sh[0]); }
}

__global__ void k_fin(const int* __restrict__ tkp) {
    int tk = *tkp;
    g_pos_min = g_minpos;
    g_neg_min = K_ - g_maxpos;
    int t = (tk < g_minpos) ? tk : g_minpos;
    g_reps = t + 1;
}

// ---------------- fp32 GEMM (packed f32x2 FMA), 128x128 tile / CTA ----------------
#define KC 32
__global__ __launch_bounds__(256, 2) void k_gemm(const float* __restrict__ A,
                                                 const float* __restrict__ Bq) {
    __shared__ float As[KC * 128];
    __shared__ float Bs[KC * 128];
    int t  = threadIdx.x;
    int nt = blockIdx.x * 128;
    int tx = t & 15, ty = t >> 4;
    int lr = t >> 3, lk4 = (t & 7) * 4;

    unsigned long long acc[8][4];
#pragma unroll
    for (int i = 0; i < 8; i++)
#pragma unroll
        for (int j = 0; j < 4; j++) acc[i][j] = 0ull;

    for (int k0 = 0; k0 < C_; k0 += KC) {
#pragma unroll
        for (int it = 0; it < 4; it++) {
            int r = it * 32 + lr;
            float4 av = *(const float4*)&A[r * C_ + k0 + lk4];
            float4 bv = *(const float4*)&Bq[(size_t)(nt + r) * C_ + k0 + lk4];
            As[(lk4 + 0) * 128 + r] = av.x; As[(lk4 + 1) * 128 + r] = av.y;
            As[(lk4 + 2) * 128 + r] = av.z; As[(lk4 + 3) * 128 + r] = av.w;
            Bs[(lk4 + 0) * 128 + r] = bv.x; Bs[(lk4 + 1) * 128 + r] = bv.y;
            Bs[(lk4 + 2) * 128 + r] = bv.z; Bs[(lk4 + 3) * 128 + r] = bv.w;
        }
        __syncthreads();
#pragma unroll
        for (int k = 0; k < KC; k++) {
            const float* ar = &As[k * 128 + ty * 8];
            const float* br = &Bs[k * 128 + tx * 8];
            float4 a0 = *(const float4*)ar, a1 = *(const float4*)(ar + 4);
            float4 b0 = *(const float4*)br, b1 = *(const float4*)(br + 4);
            unsigned long long bp0, bp1, bp2, bp3;
            PACK2(bp0, b0.x, b0.y); PACK2(bp1, b0.z, b0.w);
            PACK2(bp2, b1.x, b1.y); PACK2(bp3, b1.z, b1.w);
            float aa[8] = {a0.x, a0.y, a0.z, a0.w, a1.x, a1.y, a1.z, a1.w};
#pragma unroll
            for (int i = 0; i < 8; i++) {
                unsigned long long ap; PACK2(ap, aa[i], aa[i]);
                FMA2(acc[i][0], ap, bp0);
                FMA2(acc[i][1], ap, bp1);
                FMA2(acc[i][2], ap, bp2);
                FMA2(acc[i][3], ap, bp3);
            }
        }
        __syncthreads();
    }
#pragma unroll
    for (int i = 0; i < 8; i++) {
        int row = ty * 8 + i;
        unsigned long long* d = (unsigned long long*)&g_cos[(size_t)row * K_ + nt + tx * 8];
        d[0] = acc[i][0]; d[1] = acc[i][1]; d[2] = acc[i][2]; d[3] = acc[i][3];
    }
}

// ---------------- partition (compaction only) ----------------
__global__ __launch_bounds__(256) void k_part(const unsigned* __restrict__ lq,
                                              const unsigned* __restrict__ lQ) {
    int row = blockIdx.x >> 3;
    int chunk = blockIdx.x & 7;
    int t = threadIdx.x, lane = t & 31;
    unsigned ltm = (1u << lane) - 1u;
    int s = g_lstride;
    unsigned myl = lq[row * s];
    const float* cosr = g_cos + (size_t)row * K_ + chunk * 8192;
    for (int q = 0; q < 32; q++) {
        int col = chunk * 8192 + q * 256 + t;
        float v = cosr[q * 256 + t];
        bool isPos = (lQ[(size_t)col * s] == myl);
        unsigned negm = __ballot_sync(FULLW, !isPos);
        if (!isPos) {
            int r = __popc(negm & ltm);
            int base = 0;
            if (r == 0) base = atomicAdd(&g_neg_cnt[row], __popc(negm));
            base = __shfl_sync(negm, base, __ffs(negm) - 1);
            g_keysA[((size_t)row << 16) + base + r] = flip_f32(v);
        } else {
            unsigned posm = ~negm;
            int r = __popc(posm & ltm);
            int base = 0;
            if (r == 0) base = atomicAdd(&g_pos_wr[row], __popc(posm));
            base = __shfl_sync(posm, base, __ffs(posm) - 1);
            if (base + r < POSCAP) g_posv[row * POSCAP + base + r] = v;
        }
    }
}

// ---------------- per-quarter digit histogram for next pass ----------------
__global__ __launch_bounds__(512) void k_qhist(int srcSel, int shift) {
    int b = blockIdx.x >> 2, q = blockIdx.x & 3;
    int t = threadIdx.x, lane = t & 31;
    unsigned ltm = (1u << lane) - 1u;
    int n = g_neg_cnt[b];
    int i0 = q << 14, i1 = i0 + 16384;
    if (i1 > n) i1 = n;
    if (i1 < i0) i1 = i0;
    __shared__ unsigned h[256];
    if (t < 256) h[t] = 0;
    __syncthreads();
    const unsigned* src = (srcSel ? g_keysB : g_keysA) + ((size_t)b << 16);
    for (int base = i0; base < i1; base += 512) {
        int i = base + t;
        unsigned d = 256u;
        if (i < i1) d = (src[i] >> shift) & 255u;
        unsigned m = __match_any_sync(FULLW, d);
        if (d < 256u && (m & ltm) == 0) atomicAdd(&h[d], __popc(m));
    }
    __syncthreads();
    if (t < 256) g_qh[b][q][t] = h[t];
}

// ---------------- one stable radix pass: CTA = (row, quarter), 4 tiles ----------------
__global__ __launch_bounds__(1024) void k_pass(int srcSel, int shift) {
    int b = blockIdx.x >> 2, q = blockIdx.x & 3;
    int t = threadIdx.x, lane = t & 31, w = t >> 5;
    unsigned ltm = (1u << lane) - 1u;
    int n = g_neg_cnt[b];
    const unsigned* src = (srcSel ? g_keysB : g_keysA) + ((size_t)b << 16);
    unsigned*       dst = (srcSel ? g_keysA : g_keysB) + ((size_t)b << 16);
    int i0 = q << 14, i1 = i0 + 16384;
    if (i1 > n) i1 = n;
    if (i1 < i0) i1 = i0;

    __shared__ unsigned binbase[256];
    __shared__ unsigned tstart[256];
    __shared__ unsigned tiletot[256];
    __shared__ __align__(16) unsigned short whist[8484];
    __shared__ __align__(16) unsigned skey[TILE];

    if (w == 0) {   // global base + quarter prefix per digit
        unsigned vloc[8], pref[8], tot = 0;
#pragma unroll
        for (int c = 0; c < 8; c++) {
            int d = lane * 8 + c;
            unsigned s0 = g_qh[b][0][d], s1 = g_qh[b][1][d];
            unsigned s2 = g_qh[b][2][d], s3 = g_qh[b][3][d];
            pref[c] = (q > 0 ? s0 : 0u) + (q > 1 ? s1 : 0u) + (q > 2 ? s2 : 0u);
            unsigned td = s0 + s1 + s2 + s3;
            vloc[c] = tot; tot += td;
        }
        unsigned e = tot;
#pragma unroll
        for (int o = 1; o < 32; o <<= 1) { unsigned y = __shfl_up_sync(FULLW, e, o); if (lane >= o) e += y; }
        e -= tot;
#pragma unroll
        for (int c = 0; c < 8; c++) binbase[lane * 8 + c] = e + vloc[c] + pref[c];
    }
    __syncthreads();

    for (int tt = 0; tt < 4; tt++) {
        int base = i0 + tt * 4096;
        int tn = i1 - base;
        if (tn < 0) tn = 0;
        if (tn > TILE) tn = TILE;

        for (int z = t; z < 4242; z += 1024) ((unsigned*)whist)[z] = 0;
        __syncthreads();

        unsigned key[4], lr[4]; int dg[4];
#pragma unroll
        for (int qq = 0; qq < 4; qq++) {
            int idx = base + w * 128 + qq * 32 + lane;
            unsigned d = 256u;
            if (idx < i1) { key[qq] = src[idx]; d = (key[qq] >> shift) & 255u; }
            dg[qq] = (int)d;
            unsigned m = __match_any_sync(FULLW, d);
            unsigned r = __popc(m & ltm);
            int leader = __ffs(m) - 1;
            unsigned old = 0;
            if (r == 0) {
                old = whist[d * 33 + w];
                whist[d * 33 + w] = (unsigned short)(old + __popc(m));
            }
            old = __shfl_sync(m, old, leader);
            lr[qq] = old + r;
            __syncwarp();
        }
        __syncthreads();

        {   // column scan across 32 warps: warp w handles digits [w*8, w*8+8)
            int bd = w * 8;
            unsigned v[8], o8[8];
#pragma unroll
            for (int c = 0; c < 8; c++) { v[c] = whist[(bd + c) * 33 + lane]; o8[c] = v[c]; }
#pragma unroll
            for (int o = 1; o < 32; o <<= 1) {
#pragma unroll
                for (int c = 0; c < 8; c++) {
                    unsigned y = __shfl_up_sync(FULLW, v[c], o);
                    if (lane >= o) v[c] += y;
                }
            }
#pragma unroll
            for (int c = 0; c < 8; c++) {
                whist[(bd + c) * 33 + lane] = (unsigned short)(v[c] - o8[c]);
                if (lane == 31) tiletot[bd + c] = v[c];
            }
        }
        __syncthreads();

        if (w == 0) {   // tile-local digit starts
            unsigned vloc[8], tot = 0;
#pragma unroll
            for (int c = 0; c < 8; c++) { unsigned x = tiletot[lane * 8 + c]; vloc[c] = tot; tot += x; }
            unsigned e = tot;
#pragma unroll
            for (int o = 1; o < 32; o <<= 1) { unsigned y = __shfl_up_sync(FULLW, e, o); if (lane >= o) e += y; }
            e -= tot;
#pragma unroll
            for (int c = 0; c < 8; c++) tstart[lane * 8 + c] = e + vloc[c];
        }
        __syncthreads();

#pragma unroll
        for (int qq = 0; qq < 4; qq++) {   // stage digit-contiguous in smem
            if (dg[qq] < 256) {
                unsigned p = tstart[dg[qq]] + (unsigned)whist[dg[qq] * 33 + w] + lr[qq];
                skey[p] = key[qq];
            }
        }
        __syncthreads();

        {   // coalesced scatter
            uint4 kk = *(const uint4*)&skey[t * 4];
            unsigned ks[4] = {kk.x, kk.y, kk.z, kk.w};
            int j0 = t * 4;
#pragma unroll
            for (int qq = 0; qq < 4; qq++) {
                int j = j0 + qq;
                if (j < tn) {
                    unsigned kq = ks[qq];
                    unsigned d = (kq >> shift) & 255u;
                    dst[binbase[d] + (unsigned)j - tstart[d]] = kq;
                }
            }
        }
        __syncthreads();
        if (t < 256) binbase[t] += tiletot[t];
        __syncthreads();
    }
}

// ---------------- positives: smem bitonic sort (4096), emit pos_cat ----------------
__global__ __launch_bounds__(256) void k_possort() {
    __shared__ float s[4096];
    int b = blockIdx.x, t = threadIdx.x;
    int n = g_pos_wr[b];
    if (n > POSCAP) n = POSCAP;
    float ninf = __int_as_float(0xff800000);
    for (int i = t; i < 4096; i += 256)
        s[i] = (i < n) ? g_posv[b * POSCAP + i] : ninf;
    __syncthreads();
    for (int kk = 2; kk <= 4096; kk <<= 1) {
        for (int j = kk >> 1; j > 0; j >>= 1) {
            for (int i = t; i < 4096; i += 256) {
                int l = i ^ j;
                if (l > i) {
                    float a = s[i], c = s[l];
                    bool up = ((i & kk) == 0);
                    if (up ? (a > c) : (a < c)) { s[i] = c; s[l] = a; }
                }
            }
            __syncthreads();
        }
    }
    if (t == 0) {
        int tk = g_reps - 1;
        for (int j = 0; j < tk; j++) g_poscat[b * 32 + j] = s[4095 - j];
        g_poscat[b * 32 + tk] = s[4095 - (g_pos_min - 1)];
    }
}

// ---------------- writer: smem-broadcast, 8 segment-CTAs per b-row ----------------
__global__ __launch_bounds__(512) void k_write(float* __restrict__ out) {
    __shared__ __align__(16) float s[4096];
    int b = blockIdx.x >> 3;
    int seg = blockIdx.x & 7;
    int t = threadIdx.x;
    int reps = g_reps, nm = g_neg_min, cnt = g_neg_cnt[b];
    size_t W = (size_t)nm + 1;
    const unsigned* asc = g_keysB + ((size_t)b << 16);
    const float invT = 1.0f / 0.3f;

    if (seg == 0 && t < reps)
        out[(size_t)(b * reps + t) * W] = g_poscat[b * 32 + t] * invT;

    int per = (nm + 7) >> 3;
    int i0 = seg * per;
    int i1 = i0 + per; if (i1 > nm) i1 = nm;

    for (int c0 = i0; c0 < i1; c0 += 4096) {
        int len = i1 - c0; if (len > 4096) len = 4096;
        int glo = cnt - c0 - len;
        for (int u = t; u < len; u += 512)
            s[len - 1 - u] = unflip_f32(asc[glo + u]) * invT;
        __syncthreads();
        for (int j = 0; j < reps; j++) {
            size_t doff = (size_t)(b * reps + j) * W + 1 + c0;
            float* dst = out + doff;
            int head = (int)((4 - (doff & 3)) & 3); if (head > len) head = len;
            for (int u = t; u < head; u += 512) dst[u] = s[u];
            int nb = (len - head) >> 2;
            for (int u = t; u < nb; u += 512) {
                int p = head + u * 4;
                float4 v; v.x = s[p]; v.y = s[p + 1]; v.z = s[p + 2]; v.w = s[p + 3];
                *(float4*)&dst[p] = v;
            }
            for (int u = head + nb * 4 + t; u < len; u += 512) dst[u] = s[u];
        }
        __syncthreads();
    }
}

// ---------------- launch ----------------
extern "C" void kernel_launch(void* const* d_in, const int* in_sizes, int n_in,
                              void* d_out, int out_size) {
    const float*    A  = (const float*)d_in[0];
    const float*    Bq = (const float*)d_in[1];
    const unsigned* lq = (const unsigned*)d_in[2];
    const unsigned* lQ = (const unsigned*)d_in[3];
    const int*      tk = (const int*)d_in[4];
    float* out = (float*)d_out;
    (void)in_sizes; (void)n_in; (void)out_size;

    k_init<<<B_, 256>>>(lQ);
    k_count<<<B_, 256>>>(lq, lQ);
    k_fin<<<1, 1>>>(tk);
    k_gemm<<<K_ / 128, 256>>>(A, Bq);
    k_part<<<B_ * 8, 256>>>(lq, lQ);
    k_qhist<<<B_ * 4, 512>>>(0, 8);   k_pass<<<B_ * 4, 1024>>>(0, 8);
    k_qhist<<<B_ * 4, 512>>>(1, 16);  k_pass<<<B_ * 4, 1024>>>(1, 16);
    k_qhist<<<B_ * 4, 512>>>(0, 24);  k_pass<<<B_ * 4, 1024>>>(0, 24);
    k_possort<<<B_, 256>>>();
    k_write<<<B_ * 8, 512>>>(out);
}

// round 9
// speedup vs baseline: 1.3875x; 1.1644x over previous
#include <cuda_runtime.h>
#include <cstdint>

#define B_ 128
#define K_ 65536
#define C_ 768
#define POSCAP 4096
#define FULLW 0xffffffffu
#define TILE 4096

// ---------------- device scratch ----------------
static __device__ unsigned g_keysA[(size_t)B_ * K_];
static __device__ unsigned g_keysB[(size_t)B_ * K_];
static __device__ float    g_cos[(size_t)B_ * K_];
static __device__ float    g_posv[B_ * POSCAP];
static __device__ unsigned g_qh[3][B_][4][256];
static __device__ int      g_neg_cnt[B_];
static __device__ int      g_pos_wr[B_];
static __device__ int      g_minpos;
static __device__ int      g_maxpos;
static __device__ int      g_pos_min;
static __device__ int      g_neg_min;
static __device__ int      g_reps;
static __device__ int      g_lstride;
static __device__ float    g_poscat[B_ * 32];

__device__ __forceinline__ unsigned flip_f32(float v) {
    unsigned b = __float_as_uint(v);
    return (b & 0x80000000u) ? ~b : (b | 0x80000000u);
}
__device__ __forceinline__ float unflip_f32(unsigned u) {
    unsigned b = (u & 0x80000000u) ? (u & 0x7fffffffu) : ~u;
    return __uint_as_float(b);
}

#define PACK2(dst, lo, hi) asm("mov.b64 %0, {%1, %2};" : "=l"(dst) : "f"(lo), "f"(hi))
#define FMA2(d, a, b)      asm("fma.rn.f32x2 %0, %1, %2, %0;" : "+l"(d) : "l"(a), "l"(b))

// ---------------- init ----------------
__global__ void k_init(const unsigned* __restrict__ lQ) {
    int b = blockIdx.x, t = threadIdx.x;
    if (t == 0) { g_neg_cnt[b] = 0; g_pos_wr[b] = 0; }
#pragma unroll
    for (int i = 0; i < 3; i++)
        for (int z = t; z < 1024; z += 256)
            g_qh[i][b][z >> 8][z & 255] = 0;
    if (b == 0) {
        if (t == 0) { g_minpos = 1 << 30; g_maxpos = 0; }
        unsigned v = 0;
        for (int i = 2 * t + 1; i < 16384; i += 512) v |= lQ[i];
        __shared__ unsigned sh[256];
        sh[t] = v; __syncthreads();
        for (int o = 128; o; o >>= 1) { if (t < o) sh[t] |= sh[t + o]; __syncthreads(); }
        if (t == 0) g_lstride = (sh[0] == 0u) ? 2 : 1;
    }
}

// ---------------- per-row positive counts ----------------
__global__ void k_count(const unsigned* __restrict__ lq, const unsigned* __restrict__ lQ) {
    int b = blockIdx.x, t = threadIdx.x, s = g_lstride;
    unsigned my = lq[b * s];
    int c = 0;
    for (int k = t; k < K_; k += 256) c += (lQ[(size_t)k * s] == my);
    __shared__ int sh[256];
    sh[t] = c; __syncthreads();
    for (int o = 128; o; o >>= 1) { if (t < o) sh[t] += sh[t + o]; __syncthreads(); }
    if (t == 0) { atomicMin(&g_minpos, sh[0]); atomicMax(&g_maxpos, sh[0]); }
}

__global__ void k_fin(const int* __restrict__ tkp) {
    int tk = *tkp;
    g_pos_min = g_minpos;
    g_neg_min = K_ - g_maxpos;
    int t = (tk < g_minpos) ? tk : g_minpos;
    g_reps = t + 1;
}

// ---------------- fp32 GEMM (f32x2 FMA, XOR-swizzled smem) ----------------
#define KC 32
__global__ __launch_bounds__(256, 2) void k_gemm(const float* __restrict__ A,
                                                 const float* __restrict__ Bq) {
    __shared__ float As[KC * 128];
    __shared__ float Bs[KC * 128];
    int t  = threadIdx.x;
    int nt = blockIdx.x * 128;
    int tx = t & 15, ty = t >> 4;
    int lr = t >> 3, lk4 = (t & 7) * 4;

    unsigned long long acc[8][4];
#pragma unroll
    for (int i = 0; i < 8; i++)
#pragma unroll
        for (int j = 0; j < 4; j++) acc[i][j] = 0ull;

    for (int k0 = 0; k0 < C_; k0 += KC) {
#pragma unroll
        for (int it = 0; it < 4; it++) {
            int r = it * 32 + lr;
            int rs = r ^ lk4;   // XOR swizzle: store banks = lr^lk4, 32 distinct
            float4 av = *(const float4*)&A[r * C_ + k0 + lk4];
            float4 bv = *(const float4*)&Bq[(size_t)(nt + r) * C_ + k0 + lk4];
            As[(lk4 + 0) * 128 + rs] = av.x; As[(lk4 + 1) * 128 + rs] = av.y;
            As[(lk4 + 2) * 128 + rs] = av.z; As[(lk4 + 3) * 128 + rs] = av.w;
            Bs[(lk4 + 0) * 128 + rs] = bv.x; Bs[(lk4 + 1) * 128 + rs] = bv.y;
            Bs[(lk4 + 2) * 128 + rs] = bv.z; Bs[(lk4 + 3) * 128 + rs] = bv.w;
        }
        __syncthreads();
#pragma unroll
        for (int k = 0; k < KC; k++) {
            int fa = k & 28;
            const float* arow = &As[k * 128];
            const float* brow = &Bs[k * 128];
            int bA = (ty * 8) ^ fa;
            int bB = (tx * 8) ^ fa;
            float4 a0 = *(const float4*)&arow[bA];
            float4 a1 = *(const float4*)&arow[bA ^ 4];
            float4 b0 = *(const float4*)&brow[bB];
            float4 b1 = *(const float4*)&brow[bB ^ 4];
            unsigned long long bp0, bp1, bp2, bp3;
            PACK2(bp0, b0.x, b0.y); PACK2(bp1, b0.z, b0.w);
            PACK2(bp2, b1.x, b1.y); PACK2(bp3, b1.z, b1.w);
            float aa[8] = {a0.x, a0.y, a0.z, a0.w, a1.x, a1.y, a1.z, a1.w};
#pragma unroll
            for (int i = 0; i < 8; i++) {
                unsigned long long ap; PACK2(ap, aa[i], aa[i]);
                FMA2(acc[i][0], ap, bp0);
                FMA2(acc[i][1], ap, bp1);
                FMA2(acc[i][2], ap, bp2);
                FMA2(acc[i][3], ap, bp3);
            }
        }
        __syncthreads();
    }
#pragma unroll
    for (int i = 0; i < 8; i++) {
        int row = ty * 8 + i;
        unsigned long long* d = (unsigned long long*)&g_cos[(size_t)row * K_ + nt + tx * 8];
        d[0] = acc[i][0]; d[1] = acc[i][1]; d[2] = acc[i][2]; d[3] = acc[i][3];
    }
}

// ---------------- partition + pass-1 per-quarter histogram ----------------
__global__ __launch_bounds__(256) void k_part(const unsigned* __restrict__ lq,
                                              const unsigned* __restrict__ lQ) {
    __shared__ unsigned qh[1024];   // [quarter][digit] for pass-1 (bits 8-16)
    int row = blockIdx.x >> 3;
    int chunk = blockIdx.x & 7;
    int t = threadIdx.x, lane = t & 31;
    unsigned ltm = (1u << lane) - 1u;
    int s = g_lstride;
    unsigned myl = lq[row * s];
    for (int z = t; z < 1024; z += 256) qh[z] = 0;
    __syncthreads();
    const float* cosr = g_cos + (size_t)row * K_ + chunk * 8192;
    for (int q = 0; q < 32; q++) {
        int col = chunk * 8192 + q * 256 + t;
        float v = cosr[q * 256 + t];
        bool isPos = (lQ[(size_t)col * s] == myl);
        unsigned negm = __ballot_sync(FULLW, !isPos);
        if (!isPos) {
            int r = __popc(negm & ltm);
            int base = 0;
            if (r == 0) base = atomicAdd(&g_neg_cnt[row], __popc(negm));
            base = __shfl_sync(negm, base, __ffs(negm) - 1);
            unsigned u = flip_f32(v);
            int pos = base + r;
            g_keysA[((size_t)row << 16) + pos] = u;
            atomicAdd(&qh[((pos >> 14) << 8) | ((u >> 8) & 255u)], 1u);
        } else {
            unsigned posm = ~negm;
            int r = __popc(posm & ltm);
            int base = 0;
            if (r == 0) base = atomicAdd(&g_pos_wr[row], __popc(posm));
            base = __shfl_sync(posm, base, __ffs(posm) - 1);
            if (base + r < POSCAP) g_posv[row * POSCAP + base + r] = v;
        }
    }
    __syncthreads();
    for (int z = t; z < 1024; z += 256) {
        unsigned c = qh[z];
        if (c) atomicAdd(&g_qh[0][row][z >> 8][z & 255], c);
    }
}

// ---------------- one stable radix pass: CTA = (row, quarter), 4 tiles ----------------
// Also accumulates the NEXT pass's per-quarter histogram (by dst position).
__global__ __launch_bounds__(1024) void k_pass(int srcSel, int shift, int inIdx,
                                               int outIdx, int doNext) {
    int b = blockIdx.x >> 2, q = blockIdx.x & 3;
    int t = threadIdx.x, lane = t & 31, w = t >> 5;
    unsigned ltm = (1u << lane) - 1u;
    int n = g_neg_cnt[b];
    const unsigned* src = (srcSel ? g_keysB : g_keysA) + ((size_t)b << 16);
    unsigned*       dst = (srcSel ? g_keysA : g_keysB) + ((size_t)b << 16);
    int i0 = q << 14, i1 = i0 + 16384;
    if (i1 > n) i1 = n;
    if (i1 < i0) i1 = i0;
    int nextShift = shift + 8;

    __shared__ unsigned binbase[256];
    __shared__ unsigned tstart[256];
    __shared__ unsigned tiletot[256];
    __shared__ unsigned nh[1024];
    __shared__ __align__(16) unsigned short whist[8484];
    __shared__ __align__(16) unsigned skey[TILE];

    if (t < 1024) nh[t] = 0;
    if (w == 0) {   // global base + quarter prefix per digit
        unsigned vloc[8], pref[8], tot = 0;
#pragma unroll
        for (int c = 0; c < 8; c++) {
            int d = lane * 8 + c;
            unsigned s0 = g_qh[inIdx][b][0][d], s1 = g_qh[inIdx][b][1][d];
            unsigned s2 = g_qh[inIdx][b][2][d], s3 = g_qh[inIdx][b][3][d];
            pref[c] = (q > 0 ? s0 : 0u) + (q > 1 ? s1 : 0u) + (q > 2 ? s2 : 0u);
            unsigned td = s0 + s1 + s2 + s3;
            vloc[c] = tot; tot += td;
        }
        unsigned e = tot;
#pragma unroll
        for (int o = 1; o < 32; o <<= 1) { unsigned y = __shfl_up_sync(FULLW, e, o); if (lane >= o) e += y; }
        e -= tot;
#pragma unroll
        for (int c = 0; c < 8; c++) binbase[lane * 8 + c] = e + vloc[c] + pref[c];
    }
    __syncthreads();

    for (int tt = 0; tt < 4; tt++) {
        int base = i0 + tt * 4096;
        int tn = i1 - base;
        if (tn < 0) tn = 0;
        if (tn > TILE) tn = TILE;

        for (int z = t; z < 4242; z += 1024) ((unsigned*)whist)[z] = 0;
        __syncthreads();

        unsigned key[4], lr[4]; int dg[4];
#pragma unroll
        for (int qq = 0; qq < 4; qq++) {
            int idx = base + w * 128 + qq * 32 + lane;
            unsigned d = 256u;
            if (idx < i1) { key[qq] = src[idx]; d = (key[qq] >> shift) & 255u; }
            dg[qq] = (int)d;
            unsigned m = __match_any_sync(FULLW, d);
            unsigned r = __popc(m & ltm);
            int leader = __ffs(m) - 1;
            unsigned old = 0;
            if (r == 0) {
                old = whist[d * 33 + w];
                whist[d * 33 + w] = (unsigned short)(old + __popc(m));
            }
            old = __shfl_sync(m, old, leader);
            lr[qq] = old + r;
            __syncwarp();
        }
        __syncthreads();

        {   // column scan across 32 warps
            int bd = w * 8;
            unsigned v[8], o8[8];
#pragma unroll
            for (int c = 0; c < 8; c++) { v[c] = whist[(bd + c) * 33 + lane]; o8[c] = v[c]; }
#pragma unroll
            for (int o = 1; o < 32; o <<= 1) {
#pragma unroll
                for (int c = 0; c < 8; c++) {
                    unsigned y = __shfl_up_sync(FULLW, v[c], o);
                    if (lane >= o) v[c] += y;
                }
            }
#pragma unroll
            for (int c = 0; c < 8; c++) {
                whist[(bd + c) * 33 + lane] = (unsigned short)(v[c] - o8[c]);
                if (lane == 31) tiletot[bd + c] = v[c];
            }
        }
        __syncthreads();

        if (w == 0) {   // tile-local digit starts
            unsigned vloc[8], tot = 0;
#pragma unroll
            for (int c = 0; c < 8; c++) { unsigned x = tiletot[lane * 8 + c]; vloc[c] = tot; tot += x; }
            unsigned e = tot;
#pragma unroll
            for (int o = 1; o < 32; o <<= 1) { unsigned y = __shfl_up_sync(FULLW, e, o); if (lane >= o) e += y; }
            e -= tot;
#pragma unroll
            for (int c = 0; c < 8; c++) tstart[lane * 8 + c] = e + vloc[c];
        }
        __syncthreads();

#pragma unroll
        for (int qq = 0; qq < 4; qq++) {   // stage digit-contiguous in smem
            if (dg[qq] < 256) {
                unsigned p = tstart[dg[qq]] + (unsigned)whist[dg[qq] * 33 + w] + lr[qq];
                skey[p] = key[qq];
            }
        }
        __syncthreads();

        {   // coalesced scatter + next-pass histogram
            uint4 kk = *(const uint4*)&skey[t * 4];
            unsigned ks[4] = {kk.x, kk.y, kk.z, kk.w};
            int j0 = t * 4;
#pragma unroll
            for (int qq = 0; qq < 4; qq++) {
                int j = j0 + qq;
                if (j < tn) {
                    unsigned kq = ks[qq];
                    unsigned d = (kq >> shift) & 255u;
                    unsigned dp = binbase[d] + (unsigned)j - tstart[d];
                    dst[dp] = kq;
                    if (doNext)
                        atomicAdd(&nh[((dp >> 14) << 8) | ((kq >> nextShift) & 255u)], 1u);
                }
            }
        }
        __syncthreads();
        if (t < 256) binbase[t] += tiletot[t];
        __syncthreads();
    }
    if (doNext) {
        for (int z = t; z < 1024; z += 1024) {}
        if (t < 1024) {
            unsigned c = nh[t];
            if (c) atomicAdd(&g_qh[outIdx][b][t >> 8][t & 255], c);
        }
    }
}

// ---------------- positives: smem bitonic sort (4096), emit pos_cat ----------------
__global__ __launch_bounds__(256) void k_possort() {
    __shared__ float s[4096];
    int b = blockIdx.x, t = threadIdx.x;
    int n = g_pos_wr[b];
    if (n > POSCAP) n = POSCAP;
    float ninf = __int_as_float(0xff800000);
    for (int i = t; i < 4096; i += 256)
        s[i] = (i < n) ? g_posv[b * POSCAP + i] : ninf;
    __syncthreads();
    for (int kk = 2; kk <= 4096; kk <<= 1) {
        for (int j = kk >> 1; j > 0; j >>= 1) {
            for (int i = t; i < 4096; i += 256) {
                int l = i ^ j;
                if (l > i) {
                    float a = s[i], c = s[l];
                    bool up = ((i & kk) == 0);
                    if (up ? (a > c) : (a < c)) { s[i] = c; s[l] = a; }
                }
            }
            __syncthreads();
        }
    }
    if (t == 0) {
        int tk = g_reps - 1;
        for (int j = 0; j < tk; j++) g_poscat[b * 32 + j] = s[4095 - j];
        g_poscat[b * 32 + tk] = s[4095 - (g_pos_min - 1)];
    }
}

// ---------------- writer: smem-broadcast, 8 segment-CTAs per b-row ----------------
__global__ __launch_bounds__(512) void k_write(float* __restrict__ out) {
    __shared__ __align__(16) float s[4096];
    int b = blockIdx.x >> 3;
    int seg = blockIdx.x & 7;
    int t = threadIdx.x;
    int reps = g_reps, nm = g_neg_min, cnt = g_neg_cnt[b];
    size_t W = (size_t)nm + 1;
    const unsigned* asc = g_keysB + ((size_t)b << 16);
    const float invT = 1.0f / 0.3f;

    if (seg == 0 && t < reps)
        out[(size_t)(b * reps + t) * W] = g_poscat[b * 32 + t] * invT;

    int per = (nm + 7) >> 3;
    int i0 = seg * per;
    int i1 = i0 + per; if (i1 > nm) i1 = nm;

    for (int c0 = i0; c0 < i1; c0 += 4096) {
        int len = i1 - c0; if (len > 4096) len = 4096;
        int glo = cnt - c0 - len;
        for (int u = t; u < len; u += 512)
            s[len - 1 - u] = unflip_f32(asc[glo + u]) * invT;
        __syncthreads();
        for (int j = 0; j < reps; j++) {
            size_t doff = (size_t)(b * reps + j) * W + 1 + c0;
            float* dst = out + doff;
            int head = (int)((4 - (doff & 3)) & 3); if (head > len) head = len;
            for (int u = t; u < head; u += 512) dst[u] = s[u];
            int nb = (len - head) >> 2;
            for (int u = t; u < nb; u += 512) {
                int p = head + u * 4;
                float4 v; v.x = s[p]; v.y = s[p + 1]; v.z = s[p + 2]; v.w = s[p + 3];
                *(float4*)&dst[p] = v;
            }
            for (int u = head + nb * 4 + t; u < len; u += 512) dst[u] = s[u];
        }
        __syncthreads();
    }
}

// ---------------- launch ----------------
extern "C" void kernel_launch(void* const* d_in, const int* in_sizes, int n_in,
                              void* d_out, int out_size) {
    const float*    A  = (const float*)d_in[0];
    const float*    Bq = (const float*)d_in[1];
    const unsigned* lq = (const unsigned*)d_in[2];
    const unsigned* lQ = (const unsigned*)d_in[3];
    const int*      tk = (const int*)d_in[4];
    float* out = (float*)d_out;
    (void)in_sizes; (void)n_in; (void)out_size;

    k_init<<<B_, 256>>>(lQ);
    k_count<<<B_, 256>>>(lq, lQ);
    k_fin<<<1, 1>>>(tk);
    k_gemm<<<K_ / 128, 256>>>(A, Bq);
    k_part<<<B_ * 8, 256>>>(lq, lQ);
    k_pass<<<B_ * 4, 1024>>>(0, 8,  0, 1, 1);
    k_pass<<<B_ * 4, 1024>>>(1, 16, 1, 2, 1);
    k_pass<<<B_ * 4, 1024>>>(0, 24, 2, 2, 0);
    k_possort<<<B_, 256>>>();
    k_write<<<B_ * 8, 512>>>(out);
}